// round 16
// baseline (speedup 1.0000x reference)
#include <cuda_runtime.h>
#include <cstdint>
#include <cstddef>

#define BB 64
#define TT 512
#define AA 128
#define HH 512
#define G4 2048  // 4*H
#define NLOOP 128
#define NAUX 20
#define NCTA (NLOOP + NAUX)

typedef unsigned long long ull;

// ---------------- scratch (static device allocations) ----------------
__device__ float g_pre[(size_t)TT * G4 * BB];   // 256MB: pre-gates [t][row][b]
__device__ float g_hall[(size_t)TT * BB * HH];  // 64MB : h history [t][b][H]
__device__ ull   g_hT2[2][(HH / 2) * BB];       // recurrent h, kpair-packed
__device__ float g_wp[(size_t)BB * AA * HH];    // 16MB : W'[b]
__device__ unsigned g_flag[NLOOP];              // loop epoch flags (monotone)
__device__ unsigned g_auxflag[NAUX];            // aux epoch flags (monotone)
__device__ unsigned g_base;                     // snapshot of g_flag[0] (per launch)
__device__ unsigned g_auxbase;                  // snapshot of g_auxflag[0]

__device__ __forceinline__ void st_rel(unsigned* p, unsigned v) {
    asm volatile("st.release.gpu.global.u32 [%0], %1;" :: "l"(p), "r"(v) : "memory");
}
__device__ __forceinline__ unsigned ld_acq(const unsigned* p) {
    unsigned v;
    asm volatile("ld.acquire.gpu.global.u32 %0, [%1];" : "=r"(v) : "l"(p) : "memory");
    return v;
}
__device__ __forceinline__ void nsleep(unsigned ns) {
    asm volatile("nanosleep.u32 %0;" :: "r"(ns));
}
__device__ __forceinline__ ull fma2(ull a, ull b, ull c) {
    ull d;
    asm("fma.rn.f32x2 %0, %1, %2, %3;" : "=l"(d) : "l"(a), "l"(b), "l"(c));
    return d;
}
__device__ __forceinline__ ull add2(ull a, ull b) {
    ull d;
    asm("add.rn.f32x2 %0, %1, %2;" : "=l"(d) : "l"(a), "l"(b));
    return d;
}
__device__ __forceinline__ float2 unpack2(ull v) {
    float lo, hi;
    asm("mov.b64 {%0, %1}, %2;" : "=f"(lo), "=f"(hi) : "l"(v));
    return make_float2(lo, hi);
}
__device__ __forceinline__ float fsigmoid(float x) {
    return __fdividef(1.0f, 1.0f + __expf(-x));
}
__device__ __forceinline__ float ftanh(float x) {
    return __fdividef(2.0f, 1.0f + __expf(-2.0f * x)) - 1.0f;
}

// ---------------- kernel 1: prep = pregates + h0-pack + flag snapshot ----------------
#define NB_PRE 16384
#define NB_HIN 64

__global__ __launch_bounds__(256) void k_prep(const float* __restrict__ x,
                                              const float* __restrict__ w_ih,
                                              const float* __restrict__ b_ih,
                                              const float* __restrict__ b_hh,
                                              const float* __restrict__ h0) {
    __shared__ float As[64][68];
    __shared__ float Bs[64][68];
    const int bidg = blockIdx.x;
    const int tid = threadIdx.x;

    if (bidg < NB_PRE) {
        const int t  = bidg >> 5;
        const int n0 = (bidg & 31) * 64;
        const int tm = tid >> 4;
        const int tn = tid & 15;
        ull acc2[4][4] = {};
        for (int k0 = 0; k0 < AA; k0 += 64) {
#pragma unroll
            for (int i = 0; i < 4; i++) {
                int id = tid + i * 256;
                int r = id >> 4, c4 = (id & 15) << 2;
                *(float4*)&As[r][c4] = *(const float4*)&x[((size_t)r * TT + t) * AA + k0 + c4];
                *(float4*)&Bs[r][c4] = *(const float4*)&w_ih[(size_t)(n0 + r) * AA + k0 + c4];
            }
            __syncthreads();
#pragma unroll
            for (int k = 0; k < 64; k += 4) {
                ulonglong2 a[4], b[4];
#pragma unroll
                for (int i = 0; i < 4; i++) a[i] = *(const ulonglong2*)&As[tm * 4 + i][k];
#pragma unroll
                for (int j = 0; j < 4; j++) b[j] = *(const ulonglong2*)&Bs[tn * 4 + j][k];
#pragma unroll
                for (int i = 0; i < 4; i++)
#pragma unroll
                    for (int j = 0; j < 4; j++) {
                        acc2[i][j] = fma2(a[i].x, b[j].x, acc2[i][j]);
                        acc2[i][j] = fma2(a[i].y, b[j].y, acc2[i][j]);
                    }
            }
            __syncthreads();
        }
        float4 bi = *(const float4*)&b_ih[n0 + tn * 4];
        float4 bh = *(const float4*)&b_hh[n0 + tn * 4];
        float bias[4] = {bi.x + bh.x, bi.y + bh.y, bi.z + bh.z, bi.w + bh.w};
#pragma unroll
        for (int j = 0; j < 4; j++) {
            float r[4];
#pragma unroll
            for (int i = 0; i < 4; i++) {
                float2 u = unpack2(acc2[i][j]);
                r[i] = u.x + u.y + bias[j];
            }
            *(float4*)&g_pre[((size_t)t * G4 + n0 + tn * 4 + j) * BB + tm * 4] =
                make_float4(r[0], r[1], r[2], r[3]);
        }
    } else if (bidg < NB_PRE + NB_HIN) {
        // pack h0 into g_hT2[0]
        int id = (bidg - NB_PRE) * 256 + tid;            // 0..16383
        int kp = id >> 6, b = id & 63;
        float2 v = make_float2(h0[b * HH + 2 * kp], h0[b * HH + 2 * kp + 1]);
        ((float2*)g_hT2[0])[id] = v;
    } else {
        if (tid == 0) {
            g_base = g_flag[0];       // flags quiescent between launches
            g_auxbase = g_auxflag[0];
        }
    }
}

// ---------------- mega kernel: 128 loop CTAs + 20 aux CTAs (wprime + k_out) ----------
__global__ __launch_bounds__(512) void k_mega(const float* __restrict__ w_hh,
                                              const float* __restrict__ c0,
                                              const float* __restrict__ w_out,
                                              const float* __restrict__ Mm,
                                              const float* __restrict__ b_out,
                                              float* __restrict__ out) {
    extern __shared__ char smraw[];
    const int tid = threadIdx.x;
    const int bid = blockIdx.x;

    if (bid < NLOOP) {
        // ================= LOOP PATH (R11; hall store pre-sync, verified) ==========
        ull*        w2u   = (ull*)smraw;                   // [256 kp][64 slots]
        ull*        hs2u  = (ull*)(smraw + 131072);        // [256 kp][16 b]
        ull*        rbufU = (ull*)(smraw + 163840);        // [8 j][1032 ull]
        ulonglong2* rbuf2 = (ulonglong2*)(smraw + 163840);

        const int jg  = bid & 31;
        const int bgc = bid >> 5;
        const int j0  = jg * 16;
        const int b0  = bgc * 16;

        for (int idx = tid; idx < 64 * 256; idx += 512) {
            int rr = idx & 63, kp = idx >> 6;
            int gate = rr >> 4, ju = rr & 15;
            float2 wv = *(const float2*)(w_hh + (size_t)(gate * HH + j0 + ju) * HH + 2 * kp);
            ull v;
            asm("mov.b64 %0, {%1,%2};" : "=l"(v) : "f"(wv.x), "f"(wv.y));
            int rh = rr >> 5, rl = rr & 31;
            int slot = ((rl >> 1) & 1) * 16 + (rl >> 2) * 2 + (rl & 1);
            w2u[kp * 64 + rh * 32 + slot] = v;
        }

        const int lane = tid & 31;
        const int warp = tid >> 5;
        const int ksg  = warp >> 1;
        const int rh   = warp & 1;
        const int rql  = lane >> 2;
        const int bgl  = lane & 3;

        const int pb = tid & 15, pu = tid >> 4;
        const bool pact = (tid < 256);
        float c_reg = 0.f;
        if (pact) c_reg = c0[(size_t)(b0 + pb) * HH + j0 + pu];
        const int hT_off = ((j0 + pu) >> 1) * 128 + (b0 + pb) * 2 + ((j0 + pu) & 1);
        const int fin_bgl = pb >> 2;
        const int fin_bp  = (pb >> 1) & 1;
        const int fin_par = pb & 1;

        const unsigned e0 = ld_acq(&g_flag[bid]);
        __syncthreads();

        for (int t = 0; t < TT; ++t) {
            float pr[4];
            if (pact) {
#pragma unroll
                for (int g = 0; g < 4; g++)
                    pr[g] = __ldg(&g_pre[((size_t)t * G4 + g * HH + j0 + pu) * BB + b0 + pb]);
            }
            if (t > 0) {
                if (tid < 32) {
                    const unsigned target = e0 + (unsigned)t;
                    const unsigned* fp = &g_flag[bgc * 32 + tid];
                    while ((int)(ld_acq(fp) - target) < 0) {}
                }
                __syncthreads();
            }
            const ulonglong2* hsrc = (const ulonglong2*)g_hT2[t & 1];
            {
                ulonglong2 v[4];
#pragma unroll
                for (int i = 0; i < 4; ++i) {
                    int idx2 = tid + i * 512;
                    int kp = idx2 >> 3, blp = idx2 & 7;
                    v[i] = __ldcg(hsrc + kp * 32 + bgc * 8 + blp);
                }
#pragma unroll
                for (int i = 0; i < 4; ++i) {
                    int idx2 = tid + i * 512;
                    int kp = idx2 >> 3, blp = idx2 & 7;
                    *(ulonglong2*)(hs2u + kp * 16 + blp * 2) = v[i];
                }
            }
            __syncthreads();

            ull acc[4][4];
#pragma unroll
            for (int r = 0; r < 4; r++)
#pragma unroll
                for (int b = 0; b < 4; b++) acc[r][b] = 0ull;
            {
                const ull* hp = hs2u + (ksg * 32) * 16 + bgl * 4;
                const ull* wp = w2u + (size_t)(ksg * 32) * 64 + rh * 32 + rql * 2;
                ulonglong2 h01 = *(const ulonglong2*)(hp);
                ulonglong2 h23 = *(const ulonglong2*)(hp + 2);
                ulonglong2 w01 = *(const ulonglong2*)(wp);
                ulonglong2 w23 = *(const ulonglong2*)(wp + 16);
#pragma unroll 8
                for (int kp = 0; kp < 32; ++kp) {
                    ulonglong2 nh01, nh23, nw01, nw23;
                    if (kp < 31) {
                        nh01 = *(const ulonglong2*)(hp + (kp + 1) * 16);
                        nh23 = *(const ulonglong2*)(hp + (kp + 1) * 16 + 2);
                        nw01 = *(const ulonglong2*)(wp + (kp + 1) * 64);
                        nw23 = *(const ulonglong2*)(wp + (kp + 1) * 64 + 16);
                    }
                    ull hv[4] = {h01.x, h01.y, h23.x, h23.y};
                    ull wv[4] = {w01.x, w01.y, w23.x, w23.y};
#pragma unroll
                    for (int r = 0; r < 4; r++)
#pragma unroll
                        for (int b = 0; b < 4; b++)
                            acc[r][b] = fma2(hv[b], wv[r], acc[r][b]);
                    h01 = nh01; h23 = nh23; w01 = nw01; w23 = nw23;
                }
            }
            {
                ulonglong2* rp = rbuf2 + tid;
#pragma unroll
                for (int r = 0; r < 4; r++)
#pragma unroll
                    for (int bp = 0; bp < 2; bp++)
                        rp[(r * 2 + bp) * 516] = make_ulonglong2(acc[r][bp * 2], acc[r][bp * 2 + 1]);
            }
            __syncthreads();

            if (pact) {
                float gv[4];
#pragma unroll
                for (int g = 0; g < 4; g++) {
                    const int row  = g * 16 + pu;
                    const int rhf  = row >> 5;
                    const int rqlf = (row >> 2) & 7;
                    const int ri   = row & 3;
                    const int j    = ri * 2 + fin_bp;
                    const ull* base = rbufU + (size_t)j * 1032 + rhf * 64 + rqlf * 8
                                      + fin_bgl * 2 + fin_par;
                    ull s = base[0];
#pragma unroll
                    for (int ks = 1; ks < 8; ++ks)
                        s = add2(s, base[ks * 128]);
                    float2 u = unpack2(s);
                    gv[g] = u.x + u.y + pr[g];
                }
                float si = fsigmoid(gv[0]);
                float sf = fsigmoid(gv[1]);
                float tg = ftanh(gv[2]);
                float so = fsigmoid(gv[3]);
                c_reg = sf * c_reg + si * tg;
                float hn = so * ftanh(c_reg);
                __stcg((float*)g_hT2[(t + 1) & 1] + hT_off, hn);
                __stcg(&g_hall[(size_t)t * BB * HH + (size_t)(b0 + pb) * HH + j0 + pu], hn);
            }
            __syncthreads();
            if (tid == 0) st_rel(&g_flag[bid], e0 + (unsigned)(t + 1));
        }
    } else {
        // ===== AUX PATH: wprime, quiet barrier, then k_out with quiet polling ======
        float (*As)[68] = (float(*)[68])(smraw);
        float (*Bs)[68] = (float(*)[68])(smraw + 17408);
        const int a_id = bid - NLOOP;                    // 0..19
        const int tm = tid >> 4, tn = tid & 15;
        const bool act = (tid < 256);
        const unsigned fbase = g_base;
        const unsigned abase = g_auxbase;

        // ---- wprime tiles: W'[b] = w_out + w_out @ M[b]  (1024 tiles) ----
        for (int q = a_id; q < 1024; q += NAUX) {
            const int n0 = (q & 7) * 64;
            const int m0 = ((q >> 3) & 1) * 64;
            const int b  = q >> 4;
            float acc[4][4] = {};
            for (int k0 = 0; k0 < HH; k0 += 64) {
                if (act) {
#pragma unroll
                    for (int i = 0; i < 4; i++) {
                        int id = tid + i * 256;
                        int r = id >> 4, c4 = (id & 15) << 2;
                        *(float4*)&As[r][c4] = *(const float4*)&w_out[(size_t)(m0 + r) * HH + k0 + c4];
                        *(float4*)&Bs[r][c4] = *(const float4*)&Mm[((size_t)b * HH + k0 + r) * HH + n0 + c4];
                    }
                }
                __syncthreads();
                if (act) {
#pragma unroll
                    for (int k = 0; k < 64; k += 4) {
                        float4 a[4];
#pragma unroll
                        for (int i = 0; i < 4; i++) a[i] = *(const float4*)&As[tm * 4 + i][k];
#pragma unroll
                        for (int kk = 0; kk < 4; kk++) {
                            float4 bv = *(const float4*)&Bs[k + kk][tn * 4];
#pragma unroll
                            for (int i = 0; i < 4; i++) {
                                float av = (kk == 0) ? a[i].x : (kk == 1) ? a[i].y : (kk == 2) ? a[i].z : a[i].w;
                                acc[i][0] += av * bv.x; acc[i][1] += av * bv.y;
                                acc[i][2] += av * bv.z; acc[i][3] += av * bv.w;
                            }
                        }
                    }
                }
                __syncthreads();
            }
            if (act) {
#pragma unroll
                for (int i = 0; i < 4; i++) {
                    int m = m0 + tm * 4 + i;
                    float4 w0 = *(const float4*)&w_out[(size_t)m * HH + n0 + tn * 4];
                    float4 v = make_float4(acc[i][0] + w0.x, acc[i][1] + w0.y,
                                           acc[i][2] + w0.z, acc[i][3] + w0.w);
                    *(float4*)&g_wp[((size_t)b * AA + m) * HH + n0 + tn * 4] = v;
                }
            }
        }
        // ---- aux barrier (single-thread, nanosleep backoff) ----
        __syncthreads();
        if (tid == 0) {
            st_rel(&g_auxflag[a_id], abase + 1u);
            for (int i = 0; i < NAUX; ++i) {
                while ((int)(ld_acq(&g_auxflag[i]) - (abase + 1u)) < 0) nsleep(1000);
            }
        }
        __syncthreads();

        // ---- k_out tiles, ascending t-chunk, quiet-gated on loop epoch flags ----
        for (int q = a_id; q < 1024; q += NAUX) {
            const int tc  = q >> 7;                      // t chunk (0..7)
            const int rem = q & 127;
            const int b   = rem >> 1;
            const int n0  = (rem & 1) * 64;
            const int m0  = tc * 64;
            const int dom = b >> 4;
            if (tid == 0) {   // single quiet poller: 32 flags, nanosleep between sweeps
                const unsigned target = fbase + (unsigned)(m0 + 64);
                for (int i = 0; i < 32; ++i) {
                    const unsigned* fp = &g_flag[dom * 32 + i];
                    while ((int)(ld_acq(fp) - target) < 0) nsleep(1000);
                }
            }
            __syncthreads();

            ull acc2[4][4] = {};
            for (int k0 = 0; k0 < HH; k0 += 64) {
                if (act) {
#pragma unroll
                    for (int i = 0; i < 4; i++) {
                        int id = tid + i * 256;
                        int r = id >> 4, c4 = (id & 15) << 2;
                        *(float4*)&As[r][c4] = __ldcs((const float4*)&g_hall[((size_t)(m0 + r) * BB + b) * HH + k0 + c4]);
                        *(float4*)&Bs[r][c4] = __ldcg((const float4*)&g_wp[((size_t)b * AA + n0 + r) * HH + k0 + c4]);
                    }
                }
                __syncthreads();
                if (act) {
#pragma unroll
                    for (int k = 0; k < 64; k += 4) {
                        ulonglong2 a[4], bv[4];
#pragma unroll
                        for (int i = 0; i < 4; i++) a[i] = *(const ulonglong2*)&As[tm * 4 + i][k];
#pragma unroll
                        for (int j = 0; j < 4; j++) bv[j] = *(const ulonglong2*)&Bs[tn * 4 + j][k];
#pragma unroll
                        for (int i = 0; i < 4; i++)
#pragma unroll
                            for (int j = 0; j < 4; j++) {
                                acc2[i][j] = fma2(a[i].x, bv[j].x, acc2[i][j]);
                                acc2[i][j] = fma2(a[i].y, bv[j].y, acc2[i][j]);
                            }
                    }
                }
                __syncthreads();
            }
            if (act) {
                float4 bo = *(const float4*)&b_out[n0 + tn * 4];
                float bb[4] = {bo.x, bo.y, bo.z, bo.w};
#pragma unroll
                for (int i = 0; i < 4; i++) {
                    float r[4];
#pragma unroll
                    for (int j = 0; j < 4; j++) {
                        float2 u = unpack2(acc2[i][j]);
                        r[j] = u.x + u.y + bb[j];
                    }
                    int m = m0 + tm * 4 + i;
                    *(float4*)&out[((size_t)b * TT + m) * AA + n0 + tn * 4] =
                        make_float4(r[0], r[1], r[2], r[3]);
                }
            }
        }
    }
}

// ---------------- launch ----------------
extern "C" void kernel_launch(void* const* d_in, const int* in_sizes, int n_in,
                              void* d_out, int out_size) {
    const float* x     = (const float*)d_in[0];
    const float* w_ih  = (const float*)d_in[1];
    const float* w_hh  = (const float*)d_in[2];
    const float* b_ih  = (const float*)d_in[3];
    const float* b_hh  = (const float*)d_in[4];
    const float* Mm    = (const float*)d_in[5];
    const float* w_out = (const float*)d_in[6];
    const float* b_out = (const float*)d_in[7];
    const float* h0    = (const float*)d_in[8];
    const float* c0    = (const float*)d_in[9];
    float* out = (float*)d_out;

    const int mega_smem = 131072 + 32768 + 66048;  // 229888 B
    static int attr_done = 0;
    if (!attr_done) {
        cudaFuncSetAttribute(k_mega, cudaFuncAttributeMaxDynamicSharedMemorySize, mega_smem);
        attr_done = 1;
    }

    k_prep<<<NB_PRE + NB_HIN + 1, 256>>>(x, w_ih, b_ih, b_hh, h0);
    k_mega<<<NCTA, 512, mega_smem>>>(w_hh, c0, w_out, Mm, b_out, out);
}

// round 17
// speedup vs baseline: 1.4813x; 1.4813x over previous
#include <cuda_runtime.h>
#include <cuda_bf16.h>
#include <cstdint>
#include <cstddef>

#define BB 64
#define TT 512
#define AA 128
#define HH 512
#define G4 2048  // 4*H
#define NCTA 128

typedef unsigned long long ull;

// ---------------- scratch (static device allocations) ----------------
__device__ float g_pre[(size_t)TT * G4 * BB];   // 256MB: pre-gates [t][row][b]
__device__ float g_hall[(size_t)TT * BB * HH];  // 64MB : h history [t][b][H]
__device__ ull   g_hT2[2][(HH / 2) * BB];       // recurrent h, kpair-packed
__device__ float g_wp[(size_t)BB * AA * HH];    // 16MB : W'[b]
__device__ unsigned g_flag[NCTA];               // epoch flags (monotone)

__device__ __forceinline__ void st_rel(unsigned* p, unsigned v) {
    asm volatile("st.release.gpu.global.u32 [%0], %1;" :: "l"(p), "r"(v) : "memory");
}
__device__ __forceinline__ unsigned ld_acq(const unsigned* p) {
    unsigned v;
    asm volatile("ld.acquire.gpu.global.u32 %0, [%1];" : "=r"(v) : "l"(p) : "memory");
    return v;
}
__device__ __forceinline__ ull fma2(ull a, ull b, ull c) {
    ull d;
    asm("fma.rn.f32x2 %0, %1, %2, %3;" : "=l"(d) : "l"(a), "l"(b), "l"(c));
    return d;
}
__device__ __forceinline__ ull add2(ull a, ull b) {
    ull d;
    asm("add.rn.f32x2 %0, %1, %2;" : "=l"(d) : "l"(a), "l"(b));
    return d;
}
__device__ __forceinline__ float2 unpack2(ull v) {
    float lo, hi;
    asm("mov.b64 {%0, %1}, %2;" : "=f"(lo), "=f"(hi) : "l"(v));
    return make_float2(lo, hi);
}
__device__ __forceinline__ float fsigmoid(float x) {
    return __fdividef(1.0f, 1.0f + __expf(-x));
}
__device__ __forceinline__ float ftanh(float x) {
    return __fdividef(2.0f, 1.0f + __expf(-2.0f * x)) - 1.0f;
}
__device__ __forceinline__ unsigned short f2bf(float v) {
    __nv_bfloat16 b = __float2bfloat16_rn(v);
    return *reinterpret_cast<unsigned short*>(&b);
}
__device__ __forceinline__ float bf2f(unsigned short u) {
    __nv_bfloat16 b = *reinterpret_cast<__nv_bfloat16*>(&u);
    return __bfloat162float(b);
}
__device__ __forceinline__ uint32_t smem_u32(const void* p) {
    uint32_t a;
    asm("{ .reg .u64 t; cvta.to.shared.u64 t, %1; cvt.u32.u64 %0, t; }" : "=r"(a) : "l"(p));
    return a;
}
__device__ __forceinline__ void ldm4(uint32_t* r, uint32_t addr) {
    asm volatile("ldmatrix.sync.aligned.m8n8.x4.shared.b16 {%0,%1,%2,%3}, [%4];"
                 : "=r"(r[0]), "=r"(r[1]), "=r"(r[2]), "=r"(r[3]) : "r"(addr));
}
__device__ __forceinline__ void mma16816(float* d, const uint32_t* a, uint32_t b0, uint32_t b1) {
    asm volatile(
        "mma.sync.aligned.m16n8k16.row.col.f32.bf16.bf16.f32 "
        "{%0,%1,%2,%3}, {%4,%5,%6,%7}, {%8,%9}, {%0,%1,%2,%3};"
        : "+f"(d[0]), "+f"(d[1]), "+f"(d[2]), "+f"(d[3])
        : "r"(a[0]), "r"(a[1]), "r"(a[2]), "r"(a[3]), "r"(b0), "r"(b1));
}

// ---------------- kernel 1: merged prep = HMMA pregates + wprime + h0-pack ------------
// dyn smem (69632 B): A_hi[64][136]bf16 | A_lo | B_hi | B_lo  (rows 272B, 17x16B stride)
#define NB_PRE 16384
#define NB_WPR 1024
#define NB_HIN 64
#define PREP_SMEM 69632

__global__ __launch_bounds__(256) void k_prep(const float* __restrict__ x,
                                              const float* __restrict__ w_ih,
                                              const float* __restrict__ b_ih,
                                              const float* __restrict__ b_hh,
                                              const float* __restrict__ w_out,
                                              const float* __restrict__ Mm,
                                              const float* __restrict__ h0) {
    extern __shared__ char sm[];
    const int bidg = blockIdx.x;
    const int tid = threadIdx.x;

    if (bidg < NB_PRE) {
        // ---- HMMA pregates: pre[t][row][b] = bias[row] + sum_k w_ih[row][k]*x[b][t][k]
        char* smA_hi = sm;
        char* smA_lo = sm + 17408;
        char* smB_hi = sm + 34816;
        char* smB_lo = sm + 52224;
        const int t  = bidg >> 5;
        const int m0 = (bidg & 31) * 64;        // 64 gate rows per block

        // convert phase: 64 rows x 128 k per operand, fp32 -> bf16 hi/lo
#pragma unroll
        for (int i = 0; i < 8; i++) {
            int idx = tid + i * 256;            // 0..2047 float4 chunks
            int row = idx >> 5, c4 = (idx & 31) << 2;
            // A = w_ih rows m0+row
            float4 va = __ldg((const float4*)&w_ih[(size_t)(m0 + row) * AA + c4]);
            unsigned short h0a = f2bf(va.x), h1a = f2bf(va.y), h2a = f2bf(va.z), h3a = f2bf(va.w);
            ull hp = (ull)h0a | ((ull)h1a << 16) | ((ull)h2a << 32) | ((ull)h3a << 48);
            ull lp = (ull)f2bf(va.x - bf2f(h0a)) | ((ull)f2bf(va.y - bf2f(h1a)) << 16)
                   | ((ull)f2bf(va.z - bf2f(h2a)) << 32) | ((ull)f2bf(va.w - bf2f(h3a)) << 48);
            *(ull*)(smA_hi + row * 272 + c4 * 2) = hp;
            *(ull*)(smA_lo + row * 272 + c4 * 2) = lp;
            // B = x rows (b=row) at time t
            float4 vb = __ldg((const float4*)&x[((size_t)row * TT + t) * AA + c4]);
            unsigned short h0b = f2bf(vb.x), h1b = f2bf(vb.y), h2b = f2bf(vb.z), h3b = f2bf(vb.w);
            ull hpb = (ull)h0b | ((ull)h1b << 16) | ((ull)h2b << 32) | ((ull)h3b << 48);
            ull lpb = (ull)f2bf(vb.x - bf2f(h0b)) | ((ull)f2bf(vb.y - bf2f(h1b)) << 16)
                    | ((ull)f2bf(vb.z - bf2f(h2b)) << 32) | ((ull)f2bf(vb.w - bf2f(h3b)) << 48);
            *(ull*)(smB_hi + row * 272 + c4 * 2) = hpb;
            *(ull*)(smB_lo + row * 272 + c4 * 2) = lpb;
        }
        __syncthreads();

        // MMA phase: 8 warps = 4 m-tiles x 2 n-pairs (each n-pair = 2 n16 tiles)
        const int lane = tid & 31;
        const int warp = tid >> 5;
        const int mi = warp & 3;
        const int np = warp >> 2;
        const uint32_t smb = smem_u32(sm);
        const int a_row  = (lane & 7) + ((lane >> 3) & 1) * 8;
        const int a_koff = (lane >> 4) * 8;
        const uint32_t aHiB = smb + (uint32_t)((mi * 16 + a_row) * 136 + a_koff) * 2;
        const uint32_t aLoB = aHiB + 17408;
        const int b_n    = (lane & 7) + (lane >> 4) * 8;
        const int b_koff = ((lane >> 3) & 1) * 8;
        const uint32_t bHi0 = smb + 34816 + (uint32_t)((np * 32 + b_n) * 136 + b_koff) * 2;
        const uint32_t bHi1 = bHi0 + 16 * 272;
        const uint32_t bLo0 = bHi0 + 17408;
        const uint32_t bLo1 = bHi1 + 17408;

        float acc0a[4] = {}, acc0b[4] = {}, acc1a[4] = {}, acc1b[4] = {};
#pragma unroll
        for (int s = 0; s < 8; ++s) {
            const uint32_t off = (uint32_t)s * 32;
            uint32_t ah[4], al[4], b0h[4], b0l[4], b1h[4], b1l[4];
            ldm4(ah, aHiB + off);
            ldm4(b0h, bHi0 + off);
            ldm4(b1h, bHi1 + off);
            ldm4(al, aLoB + off);
            ldm4(b0l, bLo0 + off);
            ldm4(b1l, bLo1 + off);
            mma16816(acc0a, ah, b0h[0], b0h[1]);
            mma16816(acc0b, ah, b0h[2], b0h[3]);
            mma16816(acc1a, ah, b1h[0], b1h[1]);
            mma16816(acc1b, ah, b1h[2], b1h[3]);
            mma16816(acc0a, ah, b0l[0], b0l[1]);
            mma16816(acc0b, ah, b0l[2], b0l[3]);
            mma16816(acc1a, ah, b1l[0], b1l[1]);
            mma16816(acc1b, ah, b1l[2], b1l[3]);
            mma16816(acc0a, al, b0h[0], b0h[1]);
            mma16816(acc0b, al, b0h[2], b0h[3]);
            mma16816(acc1a, al, b1h[0], b1h[1]);
            mma16816(acc1b, al, b1h[2], b1h[3]);
            mma16816(acc0a, al, b0l[0], b0l[1]);
            mma16816(acc0b, al, b0l[2], b0l[3]);
            mma16816(acc1a, al, b1l[0], b1l[1]);
            mma16816(acc1b, al, b1l[2], b1l[3]);
        }

        // store with bias: rows prow/prow+8; cols per fragment mapping (R14-verified)
        const int prow = m0 + mi * 16 + (lane >> 2);
        const float bias0 = __ldg(&b_ih[prow]) + __ldg(&b_hh[prow]);
        const float bias1 = __ldg(&b_ih[prow + 8]) + __ldg(&b_hh[prow + 8]);
        const int pcol = np * 32 + 2 * (lane & 3);
        float* base0 = &g_pre[((size_t)t * G4 + prow) * BB];
        float* base1 = &g_pre[((size_t)t * G4 + prow + 8) * BB];
        *(float2*)(base0 + pcol)          = make_float2(acc0a[0] + bias0, acc0a[1] + bias0);
        *(float2*)(base1 + pcol)          = make_float2(acc0a[2] + bias1, acc0a[3] + bias1);
        *(float2*)(base0 + pcol + 8)      = make_float2(acc0b[0] + bias0, acc0b[1] + bias0);
        *(float2*)(base1 + pcol + 8)      = make_float2(acc0b[2] + bias1, acc0b[3] + bias1);
        *(float2*)(base0 + pcol + 16)     = make_float2(acc1a[0] + bias0, acc1a[1] + bias0);
        *(float2*)(base1 + pcol + 16)     = make_float2(acc1a[2] + bias1, acc1a[3] + bias1);
        *(float2*)(base0 + pcol + 24)     = make_float2(acc1b[0] + bias0, acc1b[1] + bias0);
        *(float2*)(base1 + pcol + 24)     = make_float2(acc1b[2] + bias1, acc1b[3] + bias1);
    } else if (bidg < NB_PRE + NB_WPR) {
        // ---- wprime: W'[b] = w_out + w_out @ M[b]  (fp32, unchanged) ----
        float (*As)[68] = (float(*)[68])sm;
        float (*Bs)[68] = (float(*)[68])(sm + 17408);
        const int q  = bidg - NB_PRE;
        const int n0 = (q & 7) * 64;
        const int m0 = ((q >> 3) & 1) * 64;
        const int b  = q >> 4;
        const int tm = tid >> 4, tn = tid & 15;
        float acc[4][4] = {};
        for (int k0 = 0; k0 < HH; k0 += 64) {
#pragma unroll
            for (int i = 0; i < 4; i++) {
                int id = tid + i * 256;
                int r = id >> 4, c4 = (id & 15) << 2;
                *(float4*)&As[r][c4] = *(const float4*)&w_out[(size_t)(m0 + r) * HH + k0 + c4];
                *(float4*)&Bs[r][c4] = *(const float4*)&Mm[((size_t)b * HH + k0 + r) * HH + n0 + c4];
            }
            __syncthreads();
#pragma unroll
            for (int k = 0; k < 64; k += 4) {
                float4 a[4];
#pragma unroll
                for (int i = 0; i < 4; i++) a[i] = *(const float4*)&As[tm * 4 + i][k];
#pragma unroll
                for (int kk = 0; kk < 4; kk++) {
                    float4 bv = *(const float4*)&Bs[k + kk][tn * 4];
#pragma unroll
                    for (int i = 0; i < 4; i++) {
                        float av = (kk == 0) ? a[i].x : (kk == 1) ? a[i].y : (kk == 2) ? a[i].z : a[i].w;
                        acc[i][0] += av * bv.x; acc[i][1] += av * bv.y;
                        acc[i][2] += av * bv.z; acc[i][3] += av * bv.w;
                    }
                }
            }
            __syncthreads();
        }
#pragma unroll
        for (int i = 0; i < 4; i++) {
            int m = m0 + tm * 4 + i;
            float4 w0 = *(const float4*)&w_out[(size_t)m * HH + n0 + tn * 4];
            float4 v = make_float4(acc[i][0] + w0.x, acc[i][1] + w0.y,
                                   acc[i][2] + w0.z, acc[i][3] + w0.w);
            *(float4*)&g_wp[((size_t)b * AA + m) * HH + n0 + tn * 4] = v;
        }
    } else {
        // ---- init: pack h0 into g_hT2[0] ----
        int id = (bidg - NB_PRE - NB_WPR) * 256 + tid;   // 0..16383
        int kp = id >> 6, b = id & 63;
        float2 v = make_float2(h0[b * HH + 2 * kp], h0[b * HH + 2 * kp + 1]);
        ((float2*)g_hT2[0])[id] = v;
    }
}

// ---------------- kernel 3: persistent recurrent loop (R11 verbatim) ----------------
__global__ __launch_bounds__(512) void k_loop(const float* __restrict__ w_hh,
                                              const float* __restrict__ c0) {
    extern __shared__ char smraw[];
    ull*        w2u   = (ull*)smraw;                   // [256 kp][64 slots]  131072 B
    ull*        hs2u  = (ull*)(smraw + 131072);        // [256 kp][16 b]      32768 B
    ull*        rbufU = (ull*)(smraw + 163840);        // [8 j][1032 ull]     66048 B
    ulonglong2* rbuf2 = (ulonglong2*)(smraw + 163840);

    const int tid = threadIdx.x;
    const int bid = blockIdx.x;
    const int jg  = bid & 31;
    const int bgc = bid >> 5;
    const int j0  = jg * 16;
    const int b0  = bgc * 16;

    for (int idx = tid; idx < 64 * 256; idx += 512) {
        int rr = idx & 63, kp = idx >> 6;
        int gate = rr >> 4, ju = rr & 15;
        float2 wv = *(const float2*)(w_hh + (size_t)(gate * HH + j0 + ju) * HH + 2 * kp);
        ull v;
        asm("mov.b64 %0, {%1,%2};" : "=l"(v) : "f"(wv.x), "f"(wv.y));
        int rh = rr >> 5, rl = rr & 31;
        int slot = ((rl >> 1) & 1) * 16 + (rl >> 2) * 2 + (rl & 1);
        w2u[kp * 64 + rh * 32 + slot] = v;
    }

    const int lane = tid & 31;
    const int warp = tid >> 5;
    const int ksg  = warp >> 1;
    const int rh   = warp & 1;
    const int rql  = lane >> 2;
    const int bgl  = lane & 3;

    const int pb = tid & 15, pu = tid >> 4;
    const bool pact = (tid < 256);
    float c_reg = 0.f;
    if (pact) c_reg = c0[(size_t)(b0 + pb) * HH + j0 + pu];
    const int hT_off = ((j0 + pu) >> 1) * 128 + (b0 + pb) * 2 + ((j0 + pu) & 1);
    const int fin_bgl = pb >> 2;
    const int fin_bp  = (pb >> 1) & 1;
    const int fin_par = pb & 1;

    const unsigned e0 = ld_acq(&g_flag[bid]);
    __syncthreads();

    for (int t = 0; t < TT; ++t) {
        if (t > 0) {
            if (tid < 32) {
                const unsigned target = e0 + (unsigned)t;
                const unsigned* fp = &g_flag[bgc * 32 + tid];
                while ((int)(ld_acq(fp) - target) < 0) {}
            }
            __syncthreads();
        }
        const ulonglong2* hsrc = (const ulonglong2*)g_hT2[t & 1];

        float pr[4];
        if (pact) {
#pragma unroll
            for (int g = 0; g < 4; g++)
                pr[g] = __ldg(&g_pre[((size_t)t * G4 + g * HH + j0 + pu) * BB + b0 + pb]);
        }

        {
            ulonglong2 v[4];
#pragma unroll
            for (int i = 0; i < 4; ++i) {
                int idx2 = tid + i * 512;
                int kp = idx2 >> 3, blp = idx2 & 7;
                v[i] = __ldcg(hsrc + kp * 32 + bgc * 8 + blp);
            }
#pragma unroll
            for (int i = 0; i < 4; ++i) {
                int idx2 = tid + i * 512;
                int kp = idx2 >> 3, blp = idx2 & 7;
                *(ulonglong2*)(hs2u + kp * 16 + blp * 2) = v[i];
            }
        }
        __syncthreads();

        ull acc[4][4];
#pragma unroll
        for (int r = 0; r < 4; r++)
#pragma unroll
            for (int b = 0; b < 4; b++) acc[r][b] = 0ull;
        {
            const ull* hp = hs2u + (ksg * 32) * 16 + bgl * 4;
            const ull* wp = w2u + (size_t)(ksg * 32) * 64 + rh * 32 + rql * 2;
            ulonglong2 h01 = *(const ulonglong2*)(hp);
            ulonglong2 h23 = *(const ulonglong2*)(hp + 2);
            ulonglong2 w01 = *(const ulonglong2*)(wp);
            ulonglong2 w23 = *(const ulonglong2*)(wp + 16);
#pragma unroll 8
            for (int kp = 0; kp < 32; ++kp) {
                ulonglong2 nh01, nh23, nw01, nw23;
                if (kp < 31) {
                    nh01 = *(const ulonglong2*)(hp + (kp + 1) * 16);
                    nh23 = *(const ulonglong2*)(hp + (kp + 1) * 16 + 2);
                    nw01 = *(const ulonglong2*)(wp + (kp + 1) * 64);
                    nw23 = *(const ulonglong2*)(wp + (kp + 1) * 64 + 16);
                }
                ull hv[4] = {h01.x, h01.y, h23.x, h23.y};
                ull wv[4] = {w01.x, w01.y, w23.x, w23.y};
#pragma unroll
                for (int r = 0; r < 4; r++)
#pragma unroll
                    for (int b = 0; b < 4; b++)
                        acc[r][b] = fma2(hv[b], wv[r], acc[r][b]);
                h01 = nh01; h23 = nh23; w01 = nw01; w23 = nw23;
            }
        }

        {
            ulonglong2* rp = rbuf2 + tid;
#pragma unroll
            for (int r = 0; r < 4; r++)
#pragma unroll
                for (int bp = 0; bp < 2; bp++)
                    rp[(r * 2 + bp) * 516] = make_ulonglong2(acc[r][bp * 2], acc[r][bp * 2 + 1]);
        }
        __syncthreads();

        float hn = 0.f;
        if (pact) {
            float gv[4];
#pragma unroll
            for (int g = 0; g < 4; g++) {
                const int row  = g * 16 + pu;
                const int rhf  = row >> 5;
                const int rqlf = (row >> 2) & 7;
                const int ri   = row & 3;
                const int j    = ri * 2 + fin_bp;
                const ull* base = rbufU + (size_t)j * 1032 + rhf * 64 + rqlf * 8
                                  + fin_bgl * 2 + fin_par;
                ull s = base[0];
#pragma unroll
                for (int ks = 1; ks < 8; ++ks)
                    s = add2(s, base[ks * 128]);
                float2 u = unpack2(s);
                gv[g] = u.x + u.y + pr[g];
            }
            float si = fsigmoid(gv[0]);
            float sf = fsigmoid(gv[1]);
            float tg = ftanh(gv[2]);
            float so = fsigmoid(gv[3]);
            c_reg = sf * c_reg + si * tg;
            hn = so * ftanh(c_reg);
            __stcg((float*)g_hT2[(t + 1) & 1] + hT_off, hn);
        }
        __syncthreads();
        if (tid == 0) st_rel(&g_flag[bid], e0 + (unsigned)(t + 1));
        if (pact)
            __stcg(&g_hall[(size_t)t * BB * HH + (size_t)(b0 + pb) * HH + j0 + pu], hn);
    }
}

// ---------------- kernel 4: out[b][t][a] = h_all[t][b] . W'[b][a] + b_out[a] (f32x2) ----
__global__ __launch_bounds__(256) void k_out(const float* __restrict__ b_out,
                                             float* __restrict__ out) {
    __shared__ float As[64][68];
    __shared__ float Bs[64][68];
    const int b  = blockIdx.z;
    const int m0 = blockIdx.y * 64;
    const int n0 = blockIdx.x * 64;
    const int tid = threadIdx.x;
    const int tm = tid >> 4, tn = tid & 15;
    ull acc2[4][4] = {};

    for (int k0 = 0; k0 < HH; k0 += 64) {
#pragma unroll
        for (int i = 0; i < 4; i++) {
            int id = tid + i * 256;
            int r = id >> 4, c4 = (id & 15) << 2;
            *(float4*)&As[r][c4] = *(const float4*)&g_hall[((size_t)(m0 + r) * BB + b) * HH + k0 + c4];
            *(float4*)&Bs[r][c4] = *(const float4*)&g_wp[((size_t)b * AA + n0 + r) * HH + k0 + c4];
        }
        __syncthreads();
#pragma unroll
        for (int k = 0; k < 64; k += 4) {
            ulonglong2 a[4], bv[4];
#pragma unroll
            for (int i = 0; i < 4; i++) a[i] = *(const ulonglong2*)&As[tm * 4 + i][k];
#pragma unroll
            for (int j = 0; j < 4; j++) bv[j] = *(const ulonglong2*)&Bs[tn * 4 + j][k];
#pragma unroll
            for (int i = 0; i < 4; i++)
#pragma unroll
                for (int j = 0; j < 4; j++) {
                    acc2[i][j] = fma2(a[i].x, bv[j].x, acc2[i][j]);
                    acc2[i][j] = fma2(a[i].y, bv[j].y, acc2[i][j]);
                }
        }
        __syncthreads();
    }
    float4 bo = *(const float4*)&b_out[n0 + tn * 4];
    float bb[4] = {bo.x, bo.y, bo.z, bo.w};
#pragma unroll
    for (int i = 0; i < 4; i++) {
        float r[4];
#pragma unroll
        for (int j = 0; j < 4; j++) {
            float2 u = unpack2(acc2[i][j]);
            r[j] = u.x + u.y + bb[j];
        }
        int m = m0 + tm * 4 + i;
        *(float4*)&out[((size_t)b * TT + m) * AA + n0 + tn * 4] =
            make_float4(r[0], r[1], r[2], r[3]);
    }
}

// ---------------- launch ----------------
extern "C" void kernel_launch(void* const* d_in, const int* in_sizes, int n_in,
                              void* d_out, int out_size) {
    const float* x     = (const float*)d_in[0];
    const float* w_ih  = (const float*)d_in[1];
    const float* w_hh  = (const float*)d_in[2];
    const float* b_ih  = (const float*)d_in[3];
    const float* b_hh  = (const float*)d_in[4];
    const float* Mm    = (const float*)d_in[5];
    const float* w_out = (const float*)d_in[6];
    const float* b_out = (const float*)d_in[7];
    const float* h0    = (const float*)d_in[8];
    const float* c0    = (const float*)d_in[9];
    float* out = (float*)d_out;

    const int loop_smem = 131072 + 32768 + 66048;  // 229888 B
    static int attr_done = 0;
    if (!attr_done) {
        cudaFuncSetAttribute(k_loop, cudaFuncAttributeMaxDynamicSharedMemorySize, loop_smem);
        cudaFuncSetAttribute(k_prep, cudaFuncAttributeMaxDynamicSharedMemorySize, PREP_SMEM);
        attr_done = 1;
    }

    k_prep<<<NB_PRE + NB_WPR + NB_HIN, 256, PREP_SMEM>>>(x, w_ih, b_ih, b_hh, w_out, Mm, h0);
    k_loop<<<NCTA, 512, loop_smem>>>(w_hh, c0);
    k_out<<<dim3(AA / 64, TT / 64, BB), 256>>>(b_out, out);
}